// round 17
// baseline (speedup 1.0000x reference)
#include <cuda_runtime.h>
#include <stdint.h>
#include <math.h>

// Problem constants (fixed by the dataset problem)
#define KST   4096   // number of states
#define NSEQ  8192   // number of sequences
#define SLEN  1024   // sequence length
#define TPB   64     // 2 warps/block (best of the cooperative TPB curve)
#define SPC   2      // sequences per CTA, run serially -> grid 4096 fits in
                     // ONE wave at 28 CTA/SM (launch_bounds caps regs at 36)

// Scratch (allocation-free rule: __device__ globals)
__device__ float g_log_init[KST];
__device__ float g_log_trans[(size_t)KST * KST];   // 64 MB, L2-resident
__device__ uint2 g_step_keys[SLEN];
__device__ float g_partial[4096];                  // per-prep-block max log

// ---------------------------------------------------------------------------
// Threefry-2x32 (20 rounds) — host/prep version
// ---------------------------------------------------------------------------
__host__ __device__ __forceinline__ uint32_t rotl32(uint32_t x, int r) {
#ifdef __CUDA_ARCH__
    return __funnelshift_l(x, x, r);
#else
    return (x << r) | (x >> (32 - r));
#endif
}

__host__ __device__ __forceinline__ void threefry2x32(
    uint32_t k0, uint32_t k1, uint32_t x0, uint32_t x1,
    uint32_t* o0, uint32_t* o1)
{
    const uint32_t k2 = k0 ^ k1 ^ 0x1BD11BDAu;
    x0 += k0; x1 += k1;
#define TF_R(r) { x0 += x1; x1 = rotl32(x1, (r)); x1 ^= x0; }
    TF_R(13) TF_R(15) TF_R(26) TF_R(6)
    x0 += k1; x1 += k2 + 1u;
    TF_R(17) TF_R(29) TF_R(16) TF_R(24)
    x0 += k2; x1 += k0 + 2u;
    TF_R(13) TF_R(15) TF_R(26) TF_R(6)
    x0 += k0; x1 += k1 + 3u;
    TF_R(17) TF_R(29) TF_R(16) TF_R(24)
    x0 += k1; x1 += k2 + 4u;
    TF_R(13) TF_R(15) TF_R(26) TF_R(6)
    x0 += k2; x1 += k0 + 5u;
#undef TF_R
    *o0 = x0; *o1 = x1;
}

// ---------------------------------------------------------------------------
// Prep: logs, step keys, per-block max into g_partial (plain deterministic
// stores — no reset kernel, no atomics needed).
// ---------------------------------------------------------------------------
__global__ void prep_kernel(const float* __restrict__ init_p,
                            const float* __restrict__ trans_p,
                            uint32_t key0x, uint32_t key0y,
                            uint32_t kloopx, uint32_t kloopy)
{
    __shared__ float sred[256];
    const long long idx    = (long long)blockIdx.x * blockDim.x + threadIdx.x;
    const long long stride = (long long)gridDim.x * blockDim.x;
    const long long total  = (long long)KST * KST;

    float lmax = -INFINITY;
    for (long long i = idx; i < total; i += stride) {
        const float l = logf(trans_p[i]);
        g_log_trans[i] = l;
        lmax = fmaxf(lmax, l);
    }
    if (idx < KST) {
        const float l = logf(init_p[idx]);
        g_log_init[idx] = l;
        lmax = fmaxf(lmax, l);
    }
    if (idx < SLEN) {
        if (idx == 0) {
            g_step_keys[0] = make_uint2(key0x, key0y);
        } else {
            uint32_t o0, o1;
            threefry2x32(kloopx, kloopy, 0u, (uint32_t)idx, &o0, &o1);
            g_step_keys[idx] = make_uint2(o0, o1);
        }
    }
    sred[threadIdx.x] = lmax;
    __syncthreads();
    for (int o = 128; o > 0; o >>= 1) {
        if (threadIdx.x < o)
            sred[threadIdx.x] = fmaxf(sred[threadIdx.x], sred[threadIdx.x + o]);
        __syncthreads();
    }
    if (threadIdx.x == 0)
        g_partial[blockIdx.x] = sred[0];
}

// ---------------------------------------------------------------------------
// Conservative bits-threshold from a mapped achieved best value.
// u_thr = exp(-exp(-(vb - R))), heavily under-padded so every skipped
// element is PROVABLY strictly below vb -> argmax unchanged bit-for-bit.
// ---------------------------------------------------------------------------
__device__ __forceinline__ uint32_t thr_from_mapped(unsigned m, float R)
{
    const unsigned ub = (m & 0x80000000u) ? (m & 0x7FFFFFFFu) : ~m;  // unmap
    const float vb = __uint_as_float(ub);
    const float t  = vb - R;
    const float w  = expf(-t);
    const float up = expf(-w) * 0.99998f;                  // >=10x composed err
    uint32_t nt = 0u;
    if (up >= 1.0f) {
        nt = 0xFFFFFFFFu;
    } else if (up > 0.0f) {
        const unsigned mant = __float_as_uint(1.0f + up) & 0x7FFFFFu;
        nt = (mant > 8u) ? ((mant - 8u) << 9) : 0u;        // extra ulp pad
    }
    return nt;   // NaN / nonpositive -> 0 (compute everything)
}

// ---------------------------------------------------------------------------
// Main sampler — R16 core (best known), TWO sequences per CTA serially.
//  - grid 4096 x 64thr, __launch_bounds__(64, 28) -> 28 CTA/SM -> ALL CTAs
//    resident in ONE wave (was 2.13 waves): no wave transition, no ragged
//    tail, perfectly balanced (each CTA = exactly 2 sequences).
//  - Per-sequence loop body byte-identical to R16: all-SHF threefry with
//    IMAD adds (runtime `one`), per-batch threshold refresh, REDUX batch
//    gate, block-shared pack argmax via atomicMax
//      pack = (mapped_value << 32) | (0x7FFFFFFF - index)
//    (value-major; ties -> smaller index == XLA first-max),
//    ONE __syncthreads per step (3-buffer rotation).
//  - Buffer (SLEN-1)%3 == 0 stays dirty at sequence end: explicit reset +
//    barrier between the two sequences (one-time cost).
// Output written as float32 (harness output dtype).
// ---------------------------------------------------------------------------
__global__ void __launch_bounds__(TPB, 28)
sample_kernel(float* __restrict__ out, uint32_t one)
{
    const int tid = threadIdx.x;

    __shared__ unsigned long long s_pack[3];
    __shared__ float s_red[TPB];

    // R = global max log, reduced from prep's per-block partials
    {
        float pm = -INFINITY;
#pragma unroll
        for (int i = 0; i < 4096 / TPB; ++i)
            pm = fmaxf(pm, g_partial[tid + i * TPB]);
        s_red[tid] = pm;
        __syncthreads();
        for (int o = TPB / 2; o > 0; o >>= 1) {
            if (tid < o) s_red[tid] = fmaxf(s_red[tid], s_red[tid + o]);
            __syncthreads();
        }
    }
    const float R = s_red[0];
    if (tid == 0) { s_pack[0] = 0ull; s_pack[1] = 0ull; s_pack[2] = 0ull; }
    __syncthreads();

    const float TINY32 = 1.17549435e-38f;               // finfo(f32).tiny

    for (int q = 0; q < SPC; ++q) {
        const int      n     = blockIdx.x + q * (NSEQ / SPC);
        const uint32_t ebase = (uint32_t)n * (uint32_t)KST;

        int prev = 0;  // unused at s=0 (uses log_init)

        for (int s = 0; s < SLEN; ++s) {
            const uint2 key = g_step_keys[s];
            const float* __restrict__ row =
                (s == 0) ? g_log_init : (g_log_trans + (size_t)prev * KST);

            const int bsel = s - (s / 3) * 3;           // s % 3
            unsigned long long* pk = &s_pack[bsel];
            const uint32_t pk_sa = (uint32_t)__cvta_generic_to_shared(pk);

            // hoisted key-injection constants
            const uint32_t k0 = key.x, k1 = key.y, kx = k0 ^ k1 ^ 0x1BD11BDAu;
            const uint32_t i1b = kx + 1u, i2b = k0 + 2u, i3b = k1 + 3u,
                           i4b = kx + 4u, i5b = k0 + 5u;
            const uint32_t x1base = k1 + ebase + (uint32_t)tid;

            unsigned last_sb = 0u;   // cached block-best (mapped)
            uint32_t bthr    = 0u;   // candidate iff bits >= bthr

#pragma unroll 4
            for (int j = 0; j < KST / TPB; ++j) {       // 64 batches
                // threefry(key, (hi=0, lo=ebase + tid + j*TPB)); x0 = k0
                uint32_t x0 = k0;
                uint32_t x1 = one * (uint32_t)(j * TPB) + x1base;
#define TFR(r) { x0 = one * x0 + x1; x1 = __funnelshift_l(x1, x1, (r)) ^ x0; }
                TFR(13) TFR(15) TFR(26) TFR(6)
                x0 = one * x0 + k1; x1 = one * x1 + i1b;
                TFR(17) TFR(29) TFR(16) TFR(24)
                x0 = one * x0 + kx; x1 = one * x1 + i2b;
                TFR(13) TFR(15) TFR(26) TFR(6)
                x0 = one * x0 + k0; x1 = one * x1 + i3b;
                TFR(17) TFR(29) TFR(16) TFR(24)
                x0 = one * x0 + k1; x1 = one * x1 + i4b;
                TFR(13) TFR(15) TFR(26) TFR(6)
                x0 = one * x0 + kx; x1 = one * x1 + i5b;
#undef TFR
                const uint32_t bits = x0 ^ x1;   // partitionable 32-bit path

                // refresh threshold from the live block-shared best
                {
                    unsigned sb;
                    asm volatile("ld.shared.b32 %0, [%1+4];"
                                 : "=r"(sb) : "r"(pk_sa));
                    if (sb > last_sb) {
                        last_sb = sb; bthr = thr_from_mapped(sb, R);
                    }
                }

                // batch gate: uniform branch, passes iff any element passes
                const uint32_t wmax = __reduce_max_sync(0xffffffffu, bits);
                if (wmax >= bthr) {
                    const bool pass = (bits >= bthr);
                    unsigned mk = 0u;
                    if (pass) {
                        // uniform(tiny,1): f = bitcast((bits>>9)|0x3f800000)-1
                        // u = max(tiny, f + tiny)  ((1-tiny)==1.0f exactly)
                        const float f =
                            __uint_as_float((bits >> 9) | 0x3f800000u) - 1.0f;
                        const float u = fmaxf(TINY32, f + TINY32);
                        const float g = -logf(-logf(u));  // libdevice logf
                        const float v = g + __ldg(row + (tid + j * TPB));
                        const unsigned ub = __float_as_uint(v);
                        mk = (ub & 0x80000000u) ? ~ub : (ub | 0x80000000u);
                    }
                    const unsigned wm = __reduce_max_sync(0xffffffffu, mk);
                    if (wm >= last_sb && wm != 0u) {
                        const unsigned sel = __ballot_sync(0xffffffffu, mk == wm);
                        const int src = __ffs(sel) - 1;  // lowest lane=lowest k
                        const int idx = (tid & ~31) + src + j * TPB;
                        const unsigned long long cand =
                            ((unsigned long long)wm << 32) |
                            (unsigned)(0x7FFFFFFF - idx);
                        atomicMax(pk, cand);
                        last_sb = wm;
                        bthr = thr_from_mapped(wm, R);
                    }
                }
            }

            __syncthreads();                 // all atomicMax done; pack final
            const unsigned long long fp = *pk;
            prev = 0x7FFFFFFF - (int)(unsigned)(fp & 0xFFFFFFFFull);
            if (tid == 0) {
                out[(size_t)n * SLEN + s] = (float)prev;  // harness dtype: f32
                s_pack[(s + 2) % 3] = 0ull;  // distance-2 reuse: race-free
            }
        }

        // between sequences: buffer (SLEN-1)%3 == 0 is still dirty
        __syncthreads();
        if (tid == 0) { s_pack[0] = 0ull; s_pack[1] = 0ull; s_pack[2] = 0ull; }
        __syncthreads();
    }
}

// ---------------------------------------------------------------------------
extern "C" void kernel_launch(void* const* d_in, const int* in_sizes, int n_in,
                              void* d_out, int out_size)
{
    const float* init_p  = (const float*)d_in[0];
    const float* trans_p = (const float*)d_in[1];
    float*       out     = (float*)d_out;

    // key = jax.random.key(42) -> threefry key (0, 42); partitionable split:
    // child i = full output pair of tf(master, (0, i))
    uint32_t a0, a1, b0, b1;
    threefry2x32(0u, 42u, 0u, 0u, &a0, &a1);   // k0    (first-state categorical)
    threefry2x32(0u, 42u, 0u, 1u, &b0, &b1);   // kloop (fold_in base)

    prep_kernel<<<4096, 256>>>(init_p, trans_p, a0, a1, b0, b1);
    sample_kernel<<<NSEQ / SPC, TPB>>>(out, 1u);
}